// round 5
// baseline (speedup 1.0000x reference)
#include <cuda_runtime.h>
#include <mma.h>
using namespace nvcuda;

#define NN 512
#define RST 516          // column stride (floats); float4 phases conflict-free

// ---------------- device scratch (no allocations allowed) ----------------
__device__ __align__(16) float2 g_slot[2 * 512 * 512];   // 4 MB
__device__ float g_U [NN * NN];
__device__ float g_Vs[NN * NN];
__device__ float g_W [NN * NN];

// ---------------- 1) cos/sin precompute into padded slots ----------------
__global__ void setup_cs_kernel(const float* __restrict__ phiU,
                                const float* __restrict__ phiV) {
    int tid = blockIdx.x * blockDim.x + threadIdx.x;
    if (tid >= 2 * 512 * 512) return;
    int mat = tid >> 18;
    int r   = tid & 262143;
    int i   = r >> 9;
    int m   = r & 511;
    float c = 1.0f, s = 0.0f;
    if (m < 511 - i) {
        int k = i * 511 - (i * (i - 1)) / 2 + m;
        float ph = mat ? __ldg(&phiV[k]) : __ldg(&phiU[k]);
        sincosf(ph, &s, &c);
    }
    g_slot[tid] = make_float2(c, s);
}

// ---------------- 2) Givens-mesh reconstruction, 8-warp chain-split ----------------
#define P2STEP(u, cc, ss) do { float _t2 = (cc)*(u); float _t1 = (ss)*(u); \
                               (u) = fmaf((ss), A, _t2); A = fmaf((cc), A, -_t1); } while (0)
#define P1STEP(u, cc, ss) do { Dw = fmaf((cc), Dw, (ss)*(u)); Cw = (cc)*Cw; } while (0)

__global__ void __launch_bounds__(256) reconstruct_kernel(const float* __restrict__ dU,
                                                          const float* __restrict__ dV,
                                                          const float* __restrict__ sigma) {
    extern __shared__ float sm[];
    float*  cols  = sm;                               // 32*RST floats
    float2* ring0 = (float2*)(sm + 32 * RST);         // 2 x 512 float2 (double buffer)
    float*  Csh   = (float*)(ring0 + 1024);           // 8
    float*  Dsh   = Csh + 8;                          // 8 x 32

    const int mat     = blockIdx.x >> 4;
    const int colbase = (blockIdx.x & 15) << 5;
    const int tid  = threadIdx.x;
    const int w    = tid >> 5;
    const int lane = tid & 31;
    const int col  = colbase + lane;

    const float4* slotf4 = (const float4*)(g_slot + mat * 262144);
    float* myc = cols + lane * RST;

    for (int r = w * 64; r < w * 64 + 64; r += 4) {
        float4 z = make_float4(0.f, 0.f, 0.f, 0.f);
        if (col >= r && col < r + 4) ((float*)&z)[col - r] = 1.0f;
        *(float4*)&myc[r] = z;
    }

    float4 pA = __ldg(&slotf4[tid]);
    float4 pB = __ldg(&slotf4[256 + tid]);

    for (int i = 0; i < 511; i++) {
        float4* rq = (float4*)(ring0 + (i & 1) * 512);
        rq[tid] = pA;
        pA = pB;
        int np = (i + 2 <= 511) ? i + 2 : 511;
        pB = __ldg(&slotf4[np * 256 + tid]);
        __syncthreads();

        const float2* ringp = ring0 + (i & 1) * 512;
        const float4* rf    = (const float4*)ringp;

        const int L  = 511 - i;
        int Lc = (((L + 7) >> 3) + 7) & ~7;
        int m0 = w * Lc;
        int m1 = m0 + Lc; if (m1 > L) m1 = L; if (m0 > L) m0 = L;

        const float A0 = myc[i];
        float Cw = 1.0f, Dw = 0.0f;

        // ---- phase 1 ----
        {
            int nfull = (m1 - m0) >> 3;
            int m = m0;
            if (nfull > 0) {
                int j = 511 - m;
                float4 va = *(float4*)&myc[j - 3];
                float4 vb = *(float4*)&myc[j - 7];
                float4 r0 = rf[(m >> 1) + 0], r1 = rf[(m >> 1) + 1];
                float4 r2 = rf[(m >> 1) + 2], r3 = rf[(m >> 1) + 3];
                for (int g = 0; g < nfull; g++) {
                    float4 nva = va, nvb = vb, n0 = r0, n1 = r1, n2 = r2, n3 = r3;
                    if (g + 1 < nfull) {
                        int mn = m + 8, jn = 511 - mn;
                        n0 = rf[(mn >> 1) + 0]; n1 = rf[(mn >> 1) + 1];
                        n2 = rf[(mn >> 1) + 2]; n3 = rf[(mn >> 1) + 3];
                        nva = *(float4*)&myc[jn - 3];
                        nvb = *(float4*)&myc[jn - 7];
                    }
                    P1STEP(va.w, r0.x, r0.y);  P1STEP(va.z, r0.z, r0.w);
                    P1STEP(va.y, r1.x, r1.y);  P1STEP(va.x, r1.z, r1.w);
                    P1STEP(vb.w, r2.x, r2.y);  P1STEP(vb.z, r2.z, r2.w);
                    P1STEP(vb.y, r3.x, r3.y);  P1STEP(vb.x, r3.z, r3.w);
                    va = nva; vb = nvb; r0 = n0; r1 = n1; r2 = n2; r3 = n3;
                    m += 8;
                }
            }
            for (; m < m1; m++) {
                float2 p = ringp[m];
                float  u = myc[511 - m];
                Dw = fmaf(p.x, Dw, p.y * u);
                Cw = p.x * Cw;
            }
        }

        // ---- stitch ----
        if (lane == 0) Csh[w] = Cw;
        Dsh[w * 32 + lane] = Dw;
        __syncthreads();
        float A = A0;
        #pragma unroll 7
        for (int kk = 0; kk < w; kk++)
            A = fmaf(Csh[kk], A, -Dsh[kk * 32 + lane]);
        if (w == 7) myc[i] = fmaf(Cw, A, -Dw);

        // ---- phase 2 ----
        {
            int nfull = (m1 - m0) >> 3;
            int m = m0;
            if (nfull > 0) {
                int j = 511 - m;
                float4 va = *(float4*)&myc[j - 3];
                float4 vb = *(float4*)&myc[j - 7];
                float4 r0 = rf[(m >> 1) + 0], r1 = rf[(m >> 1) + 1];
                float4 r2 = rf[(m >> 1) + 2], r3 = rf[(m >> 1) + 3];
                for (int g = 0; g < nfull; g++) {
                    float4 nva = va, nvb = vb, n0 = r0, n1 = r1, n2 = r2, n3 = r3;
                    if (g + 1 < nfull) {
                        int mn = m + 8, jn = 511 - mn;
                        n0 = rf[(mn >> 1) + 0]; n1 = rf[(mn >> 1) + 1];
                        n2 = rf[(mn >> 1) + 2]; n3 = rf[(mn >> 1) + 3];
                        nva = *(float4*)&myc[jn - 3];
                        nvb = *(float4*)&myc[jn - 7];
                    }
                    P2STEP(va.w, r0.x, r0.y);  P2STEP(va.z, r0.z, r0.w);
                    P2STEP(va.y, r1.x, r1.y);  P2STEP(va.x, r1.z, r1.w);
                    P2STEP(vb.w, r2.x, r2.y);  P2STEP(vb.z, r2.z, r2.w);
                    P2STEP(vb.y, r3.x, r3.y);  P2STEP(vb.x, r3.z, r3.w);
                    int jj = 511 - m;
                    *(float4*)&myc[jj - 3] = va;
                    *(float4*)&myc[jj - 7] = vb;
                    va = nva; vb = nvb; r0 = n0; r1 = n1; r2 = n2; r3 = n3;
                    m += 8;
                }
            }
            for (; m < m1; m++) {
                float2 p = ringp[m];
                int jj = 511 - m;
                float u = myc[jj];
                float t2 = p.x * u, t1 = p.y * u;
                myc[jj] = fmaf(p.y, A, t2);
                A = fmaf(p.x, A, -t1);
            }
        }
    }
    __syncthreads();

    if (mat == 0) {
        for (int r = w * 64; r < w * 64 + 64; r++)
            g_U[r * NN + col] = __ldg(&dU[r]) * myc[r];
    } else {
        for (int r = w * 64; r < w * 64 + 64; r++)
            g_Vs[r * NN + col] = __ldg(&sigma[r]) * __ldg(&dV[r]) * myc[r];
    }
}

// ---------------- 3) W = U @ (sigma*delta_V * V) ----------------
__global__ void wgemm_kernel() {
    __shared__ float As[32][33];
    __shared__ float Bs[32][33];
    const int tx = threadIdx.x, ty = threadIdx.y;
    const int a = blockIdx.y * 32 + ty;
    const int b = blockIdx.x * 32 + tx;
    float acc = 0.0f;
    for (int kt = 0; kt < NN; kt += 32) {
        As[ty][tx] = g_U [a * NN + kt + tx];
        Bs[ty][tx] = g_Vs[(kt + ty) * NN + b];
        __syncthreads();
        #pragma unroll
        for (int kk = 0; kk < 32; kk++)
            acc += As[ty][kk] * Bs[kk][tx];
        __syncthreads();
    }
    g_W[a * NN + b] = acc;
}

// ---------------- 4) out = x @ W^T via 3xTF32 wmma tensor cores ----------------
#define BM 128
#define BN 128
#define BK 16
#define SLD 20

__global__ void __launch_bounds__(256) tfgemm_kernel(const float* __restrict__ A,
                                                     float* __restrict__ C) {
    __shared__ float xhi[BM][SLD], xlo[BM][SLD];
    __shared__ float whi[BN][SLD], wlo[BN][SLD];
    const float* __restrict__ Wg = g_W;

    const int tid  = threadIdx.x;
    const int warp = tid >> 5;
    const int m0 = blockIdx.y * BM;
    const int n0 = blockIdx.x * BN;

    const int wm = (warp >> 2) * 64;   // 2 warps in m
    const int wn = (warp & 3) * 32;    // 4 warps in n

    wmma::fragment<wmma::accumulator, 16, 16, 8, float> acc[4][2];
    #pragma unroll
    for (int i = 0; i < 4; i++)
        #pragma unroll
        for (int j = 0; j < 2; j++) wmma::fill_fragment(acc[i][j], 0.0f);

    const int lr = tid >> 2;
    const int lc = (tid & 3) << 2;
    const float* Ap = A  + (m0 + lr) * NN + lc;
    const float* Wp = Wg + (n0 + lr) * NN + lc;

    for (int k0 = 0; k0 < NN; k0 += BK) {
        #pragma unroll
        for (int h = 0; h < 2; h++) {
            float4 v  = *(const float4*)(Ap + h * 64 * NN + k0);
            float4 ww = *(const float4*)(Wp + h * 64 * NN + k0);
            int r = lr + h * 64;
            #pragma unroll
            for (int e = 0; e < 4; e++) {
                float xv = ((const float*)&v)[e];
                float hi = wmma::__float_to_tf32(xv);
                xhi[r][lc + e] = hi;
                xlo[r][lc + e] = wmma::__float_to_tf32(xv - hi);
                float wv = ((const float*)&ww)[e];
                float wh = wmma::__float_to_tf32(wv);
                whi[r][lc + e] = wh;
                wlo[r][lc + e] = wmma::__float_to_tf32(wv - wh);
            }
        }
        __syncthreads();

        #pragma unroll
        for (int ks = 0; ks < BK; ks += 8) {
            wmma::fragment<wmma::matrix_a, 16, 16, 8, wmma::precision::tf32, wmma::row_major> ah[4], al[4];
            wmma::fragment<wmma::matrix_b, 16, 16, 8, wmma::precision::tf32, wmma::col_major> bh[2], bl[2];
            #pragma unroll
            for (int i = 0; i < 4; i++) {
                wmma::load_matrix_sync(ah[i], &xhi[wm + i * 16][ks], SLD);
                wmma::load_matrix_sync(al[i], &xlo[wm + i * 16][ks], SLD);
            }
            #pragma unroll
            for (int j = 0; j < 2; j++) {
                wmma::load_matrix_sync(bh[j], &whi[wn + j * 16][ks], SLD);
                wmma::load_matrix_sync(bl[j], &wlo[wn + j * 16][ks], SLD);
            }
            #pragma unroll
            for (int i = 0; i < 4; i++)
                #pragma unroll
                for (int j = 0; j < 2; j++) {
                    wmma::mma_sync(acc[i][j], ah[i], bh[j], acc[i][j]);
                    wmma::mma_sync(acc[i][j], ah[i], bl[j], acc[i][j]);
                    wmma::mma_sync(acc[i][j], al[i], bh[j], acc[i][j]);
                }
        }
        __syncthreads();
    }

    #pragma unroll
    for (int i = 0; i < 4; i++)
        #pragma unroll
        for (int j = 0; j < 2; j++)
            wmma::store_matrix_sync(&C[(m0 + wm + i * 16) * NN + n0 + wn + j * 16],
                                    acc[i][j], NN, wmma::mem_row_major);
}

// ---------------- launch ----------------
extern "C" void kernel_launch(void* const* d_in, const int* in_sizes, int n_in,
                              void* d_out, int out_size) {
    const float* x     = (const float*)d_in[0];
    const float* phiU  = (const float*)d_in[1];
    const float* dU    = (const float*)d_in[2];
    const float* phiV  = (const float*)d_in[3];
    const float* dV    = (const float*)d_in[4];
    const float* sigma = (const float*)d_in[5];
    float* out = (float*)d_out;

    const int recon_smem = 32 * RST * 4 + 1024 * 8 + (8 + 256) * 4;   // 75296 B
    cudaFuncSetAttribute(reconstruct_kernel,
                         cudaFuncAttributeMaxDynamicSharedMemorySize, recon_smem);

    setup_cs_kernel<<<(2 * 512 * 512 + 255) / 256, 256>>>(phiU, phiV);
    reconstruct_kernel<<<32, 256, recon_smem>>>(dU, dV, sigma);
    wgemm_kernel<<<dim3(16, 16), dim3(32, 32)>>>();
    tfgemm_kernel<<<dim3(NN / BN, 32768 / BM), 256>>>(x, out);
}